// round 3
// baseline (speedup 1.0000x reference)
#include <cuda_runtime.h>
#include <math_constants.h>

#define APW 512             // atoms per warp (contiguous chunk)
#define THREADS_MAIN 256    // 8 warps per block

// Scratch: per-segment atom counts. BATCH = out_size/256 = 16384; pad to 64K.
__device__ float g_counts[65536];

__device__ __forceinline__ void atomic_max_float(float* addr, float v) {
    // Valid given init to -inf: non-negative floats order as ints,
    // negative floats reverse-order as unsigned ints.
    if (v >= 0.0f) atomicMax((int*)addr, __float_as_int(v));
    else           atomicMin((unsigned int*)addr, __float_as_uint(v));
}

// ---------------------------------------------------------------------------
// Init (vectorized): mean half = 0, max half = -inf, counts = 0
// out viewed as float4: 64 per row; first 32 = sums, last 32 = -inf
// ---------------------------------------------------------------------------
__global__ void gg_init(float4* __restrict__ out4, int batch) {
    int i = blockIdx.x * blockDim.x + threadIdx.x;
    int total = batch * 64;
    if (i < total) {
        bool mean_half = (i & 63) < 32;
        float v = mean_half ? 0.0f : -CUDART_INF_F;
        out4[i] = make_float4(v, v, v, v);
    }
    if (i < batch) g_counts[i] = 0.0f;
}

// ---------------------------------------------------------------------------
// Main: warp-per-chunk segmented scan.
// Lane l owns features [4l, 4l+4) via float4. Segments fully inside a chunk
// flush with plain stores; boundary segments flush with atomics.
// ---------------------------------------------------------------------------
__global__ void __launch_bounds__(THREADS_MAIN, 3)
gg_main(const float* __restrict__ feat,
        const int*   __restrict__ mem,
        float*       __restrict__ out,
        int n_atoms) {
    const int lane = threadIdx.x & 31;
    const long long wg = (long long)((blockIdx.x * blockDim.x + threadIdx.x) >> 5);
    long long astart = wg * APW;
    if (astart >= n_atoms) return;
    long long aend = astart + APW;
    if (aend > n_atoms) aend = n_atoms;

    const float4* __restrict__ frow = (const float4*)feat;  // 32 float4 per row

    int  seg = __ldg(mem + astart);
    bool began_inside = (astart == 0) || (__ldg(mem + astart - 1) != seg);

    float4 s = make_float4(0.f, 0.f, 0.f, 0.f);
    float4 m = make_float4(-CUDART_INF_F, -CUDART_INF_F, -CUDART_INF_F, -CUDART_INF_F);
    int cnt = 0;

    auto flush = [&](int sg, bool full) {
        float* om = out + (size_t)sg * 256 + lane * 4;   // mean(sum) slot
        float* ox = om + 128;                            // max slot
        if (full) {
            *(float4*)om = s;
            *(float4*)ox = m;
            if (lane == 0) g_counts[sg] = (float)cnt;
        } else {
            atomicAdd(om + 0, s.x); atomicAdd(om + 1, s.y);
            atomicAdd(om + 2, s.z); atomicAdd(om + 3, s.w);
            atomic_max_float(ox + 0, m.x); atomic_max_float(ox + 1, m.y);
            atomic_max_float(ox + 2, m.z); atomic_max_float(ox + 3, m.w);
            if (lane == 0) atomicAdd(&g_counts[sg], (float)cnt);
        }
    };

    long long a = astart;
    // Unroll-8 main loop: batch all loads first for MLP=8 LDG.128 per lane.
    for (; a + 8 <= aend; a += 8) {
        int4 mb0 = *(const int4*)(mem + a);
        int4 mb1 = *(const int4*)(mem + a + 4);
        float4 vv[8];
#pragma unroll
        for (int u = 0; u < 8; ++u)
            vv[u] = __ldg(&frow[(a + u) * 32 + lane]);
        int mbs[8] = {mb0.x, mb0.y, mb0.z, mb0.w, mb1.x, mb1.y, mb1.z, mb1.w};
#pragma unroll
        for (int u = 0; u < 8; ++u) {
            if (mbs[u] != seg) {
                flush(seg, began_inside);
                began_inside = true;
                seg = mbs[u];
                s = make_float4(0.f, 0.f, 0.f, 0.f);
                m = make_float4(-CUDART_INF_F, -CUDART_INF_F, -CUDART_INF_F, -CUDART_INF_F);
                cnt = 0;
            }
            s.x += vv[u].x; s.y += vv[u].y; s.z += vv[u].z; s.w += vv[u].w;
            m.x = fmaxf(m.x, vv[u].x); m.y = fmaxf(m.y, vv[u].y);
            m.z = fmaxf(m.z, vv[u].z); m.w = fmaxf(m.w, vv[u].w);
            ++cnt;
        }
    }
    // Scalar tail (only if chunk size not divisible by 8)
    for (; a < aend; ++a) {
        int mb = __ldg(mem + a);
        float4 v = __ldg(&frow[a * 32 + lane]);
        if (mb != seg) {
            flush(seg, began_inside);
            began_inside = true;
            seg = mb;
            s = make_float4(0.f, 0.f, 0.f, 0.f);
            m = make_float4(-CUDART_INF_F, -CUDART_INF_F, -CUDART_INF_F, -CUDART_INF_F);
            cnt = 0;
        }
        s.x += v.x; s.y += v.y; s.z += v.z; s.w += v.w;
        m.x = fmaxf(m.x, v.x); m.y = fmaxf(m.y, v.y);
        m.z = fmaxf(m.z, v.z); m.w = fmaxf(m.w, v.w);
        ++cnt;
    }

    bool ended_inside = (aend == n_atoms) || (__ldg(mem + aend) != seg);
    flush(seg, began_inside && ended_inside);
}

// ---------------------------------------------------------------------------
// Finalize (vectorized): mean = sum / count. One float4 per thread over the
// mean half only (32 float4s per segment row of 64).
// ---------------------------------------------------------------------------
__global__ void gg_fin(float4* __restrict__ out4, int batch) {
    int i = blockIdx.x * blockDim.x + threadIdx.x;
    int total = batch * 32;
    if (i < total) {
        int sg = i >> 5;
        int f  = i & 31;
        float r = 1.0f / __ldg(&g_counts[sg]);
        float4 v = out4[(size_t)sg * 64 + f];
        v.x *= r; v.y *= r; v.z *= r; v.w *= r;
        out4[(size_t)sg * 64 + f] = v;
    }
}

// ---------------------------------------------------------------------------
extern "C" void kernel_launch(void* const* d_in, const int* in_sizes, int n_in,
                              void* d_out, int out_size) {
    const float* feat = (const float*)d_in[0];
    const int*   mem  = (const int*)d_in[1];
    float*       out  = (float*)d_out;

    int n_atoms = in_sizes[1];          // membership element count
    int batch   = out_size / 256;       // output rows ([batch, 2*128])

    int init_total = batch * 64;        // float4 count
    gg_init<<<(init_total + 255) / 256, 256>>>((float4*)out, batch);

    long long nwarps   = ((long long)n_atoms + APW - 1) / APW;
    long long nthreads = nwarps * 32;
    int nblocks = (int)((nthreads + THREADS_MAIN - 1) / THREADS_MAIN);
    gg_main<<<nblocks, THREADS_MAIN>>>(feat, mem, out, n_atoms);

    int fin_total = batch * 32;         // float4 count (mean half)
    gg_fin<<<(fin_total + 255) / 256, 256>>>((float4*)out, batch);
}

// round 4
// speedup vs baseline: 1.1611x; 1.1611x over previous
#include <cuda_runtime.h>
#include <math_constants.h>

#define THREADS_MAIN 256    // 8 warps per block
#define BLOCKS_PER_SM 2

// Scratch: per-segment atom counts. BATCH = out_size/256 = 16384; pad to 64K.
__device__ float g_counts[65536];

__device__ __forceinline__ void atomic_max_float(float* addr, float v) {
    // Valid given init to -inf: non-negative floats order as ints,
    // negative floats reverse-order as unsigned ints.
    if (v >= 0.0f) atomicMax((int*)addr, __float_as_int(v));
    else           atomicMin((unsigned int*)addr, __float_as_uint(v));
}

// ---------------------------------------------------------------------------
// Init (vectorized): mean half = 0, max half = -inf, counts = 0
// ---------------------------------------------------------------------------
__global__ void gg_init(float4* __restrict__ out4, int batch) {
    int i = blockIdx.x * blockDim.x + threadIdx.x;
    int total = batch * 64;
    if (i < total) {
        bool mean_half = (i & 63) < 32;
        float v = mean_half ? 0.0f : -CUDART_INF_F;
        out4[i] = make_float4(v, v, v, v);
    }
    if (i < batch) g_counts[i] = 0.0f;
}

// ---------------------------------------------------------------------------
// Main: warp-per-chunk segmented scan, chunk size passed in (multiple of 8).
// Lane l owns features [4l, 4l+4) via float4. Segments fully inside a chunk
// flush with plain stores; boundary segments flush with atomics.
// ---------------------------------------------------------------------------
__global__ void gg_main(const float* __restrict__ feat,
                        const int*   __restrict__ mem,
                        float*       __restrict__ out,
                        int n_atoms, int chunk) {
    const int lane = threadIdx.x & 31;
    const long long wg = (long long)((blockIdx.x * blockDim.x + threadIdx.x) >> 5);
    long long astart = wg * chunk;
    if (astart >= n_atoms) return;
    long long aend = astart + chunk;
    if (aend > n_atoms) aend = n_atoms;

    const float4* __restrict__ frow = (const float4*)feat;  // 32 float4 per row

    int  seg = __ldg(mem + astart);
    bool began_inside = (astart == 0) || (__ldg(mem + astart - 1) != seg);

    float4 s = make_float4(0.f, 0.f, 0.f, 0.f);
    float4 m = make_float4(-CUDART_INF_F, -CUDART_INF_F, -CUDART_INF_F, -CUDART_INF_F);
    int cnt = 0;

    auto flush = [&](int sg, bool full) {
        float* om = out + (size_t)sg * 256 + lane * 4;   // mean(sum) slot
        float* ox = om + 128;                            // max slot
        if (full) {
            *(float4*)om = s;
            *(float4*)ox = m;
            if (lane == 0) g_counts[sg] = (float)cnt;
        } else {
            atomicAdd(om + 0, s.x); atomicAdd(om + 1, s.y);
            atomicAdd(om + 2, s.z); atomicAdd(om + 3, s.w);
            atomic_max_float(ox + 0, m.x); atomic_max_float(ox + 1, m.y);
            atomic_max_float(ox + 2, m.z); atomic_max_float(ox + 3, m.w);
            if (lane == 0) atomicAdd(&g_counts[sg], (float)cnt);
        }
    };

    long long a = astart;
    // Unroll-8 main loop: batch all loads first for MLP=8 LDG.128 per lane.
    for (; a + 8 <= aend; a += 8) {
        int4 mb0 = *(const int4*)(mem + a);
        int4 mb1 = *(const int4*)(mem + a + 4);
        float4 vv[8];
#pragma unroll
        for (int u = 0; u < 8; ++u)
            vv[u] = __ldg(&frow[(a + u) * 32 + lane]);
        int mbs[8] = {mb0.x, mb0.y, mb0.z, mb0.w, mb1.x, mb1.y, mb1.z, mb1.w};
#pragma unroll
        for (int u = 0; u < 8; ++u) {
            if (mbs[u] != seg) {
                flush(seg, began_inside);
                began_inside = true;
                seg = mbs[u];
                s = make_float4(0.f, 0.f, 0.f, 0.f);
                m = make_float4(-CUDART_INF_F, -CUDART_INF_F, -CUDART_INF_F, -CUDART_INF_F);
                cnt = 0;
            }
            s.x += vv[u].x; s.y += vv[u].y; s.z += vv[u].z; s.w += vv[u].w;
            m.x = fmaxf(m.x, vv[u].x); m.y = fmaxf(m.y, vv[u].y);
            m.z = fmaxf(m.z, vv[u].z); m.w = fmaxf(m.w, vv[u].w);
            ++cnt;
        }
    }
    // Scalar tail (only for the last warp when n not divisible by 8)
    for (; a < aend; ++a) {
        int mb = __ldg(mem + a);
        float4 v = __ldg(&frow[a * 32 + lane]);
        if (mb != seg) {
            flush(seg, began_inside);
            began_inside = true;
            seg = mb;
            s = make_float4(0.f, 0.f, 0.f, 0.f);
            m = make_float4(-CUDART_INF_F, -CUDART_INF_F, -CUDART_INF_F, -CUDART_INF_F);
            cnt = 0;
        }
        s.x += v.x; s.y += v.y; s.z += v.z; s.w += v.w;
        m.x = fmaxf(m.x, v.x); m.y = fmaxf(m.y, v.y);
        m.z = fmaxf(m.z, v.z); m.w = fmaxf(m.w, v.w);
        ++cnt;
    }

    bool ended_inside = (aend == n_atoms) || (__ldg(mem + aend) != seg);
    flush(seg, began_inside && ended_inside);
}

// ---------------------------------------------------------------------------
// Finalize (vectorized): mean = sum / count over the mean half only.
// ---------------------------------------------------------------------------
__global__ void gg_fin(float4* __restrict__ out4, int batch) {
    int i = blockIdx.x * blockDim.x + threadIdx.x;
    int total = batch * 32;
    if (i < total) {
        int sg = i >> 5;
        int f  = i & 31;
        float r = 1.0f / __ldg(&g_counts[sg]);
        float4 v = out4[(size_t)sg * 64 + f];
        v.x *= r; v.y *= r; v.z *= r; v.w *= r;
        out4[(size_t)sg * 64 + f] = v;
    }
}

// ---------------------------------------------------------------------------
extern "C" void kernel_launch(void* const* d_in, const int* in_sizes, int n_in,
                              void* d_out, int out_size) {
    const float* feat = (const float*)d_in[0];
    const int*   mem  = (const int*)d_in[1];
    float*       out  = (float*)d_out;

    int n_atoms = in_sizes[1];          // membership element count
    int batch   = out_size / 256;       // output rows ([batch, 2*128])

    // Exactly-balanced single wave: SM_count * BLOCKS_PER_SM blocks, 8 warps each.
    int sm_count = 152;
    cudaDeviceGetAttribute(&sm_count, cudaDevAttrMultiProcessorCount, 0);
    int nblocks = sm_count * BLOCKS_PER_SM;
    long long nwarps = (long long)nblocks * (THREADS_MAIN / 32);
    long long chunk_ll = (n_atoms + nwarps - 1) / nwarps;
    int chunk = (int)((chunk_ll + 7) / 8) * 8;   // multiple of 8

    int init_total = batch * 64;        // float4 count
    gg_init<<<(init_total + 255) / 256, 256>>>((float4*)out, batch);

    gg_main<<<nblocks, THREADS_MAIN>>>(feat, mem, out, n_atoms, chunk);

    int fin_total = batch * 32;         // float4 count (mean half)
    gg_fin<<<(fin_total + 255) / 256, 256>>>((float4*)out, batch);
}

// round 5
// speedup vs baseline: 1.1664x; 1.0046x over previous
#include <cuda_runtime.h>
#include <math_constants.h>

#define THREADS_MAIN 256    // 8 warps per block
#define BLOCKS_PER_SM 2

// Scratch: per-segment atom counts + boundary flags. batch=16384; pad to 64K.
__device__ float         g_counts[65536];
__device__ unsigned char g_flag[65536];

__device__ __forceinline__ void atomic_max_float(float* addr, float v) {
    // Valid given init to -inf: non-negative floats order as ints,
    // negative floats reverse-order as unsigned ints.
    if (v >= 0.0f) atomicMax((int*)addr, __float_as_int(v));
    else           atomicMin((unsigned int*)addr, __float_as_uint(v));
}

__device__ __forceinline__ void f32x2_add(unsigned long long& acc, unsigned long long v) {
    asm("add.rn.f32x2 %0, %0, %1;" : "+l"(acc) : "l"(v));
}
__device__ __forceinline__ float2 unpack2(unsigned long long v) {
    float a, b;
    asm("mov.b64 {%0,%1}, %2;" : "=f"(a), "=f"(b) : "l"(v));
    return make_float2(a, b);
}

// ---------------------------------------------------------------------------
// Init: each thread writes one mean float4 (0) and one max float4 (-inf).
// ---------------------------------------------------------------------------
__global__ void gg_init(float4* __restrict__ out4, int batch) {
    int i = blockIdx.x * blockDim.x + threadIdx.x;
    int total = batch * 32;
    if (i < total) {
        int sg = i >> 5, f = i & 31;
        size_t base = (size_t)sg * 64 + f;
        out4[base]      = make_float4(0.f, 0.f, 0.f, 0.f);
        out4[base + 32] = make_float4(-CUDART_INF_F, -CUDART_INF_F,
                                      -CUDART_INF_F, -CUDART_INF_F);
    }
    if (i < batch) { g_counts[i] = 0.0f; g_flag[i] = 0; }
}

// ---------------------------------------------------------------------------
// Main: warp-per-chunk segmented scan. Lane l owns features [4l,4l+4).
// Sorted membership -> warp-uniform fast path when an 8-batch is one segment.
// Interior segments: plain stores with mean divided in-place.
// Boundary segments: atomics + flag for the fin pass.
// ---------------------------------------------------------------------------
__global__ void gg_main(const float* __restrict__ feat,
                        const int*   __restrict__ mem,
                        float*       __restrict__ out,
                        int n_atoms, int chunk) {
    const int lane = threadIdx.x & 31;
    const long long wg = (long long)((blockIdx.x * blockDim.x + threadIdx.x) >> 5);
    long long astart = wg * chunk;
    if (astart >= n_atoms) return;
    long long aend = astart + chunk;
    if (aend > n_atoms) aend = n_atoms;

    const ulonglong2* __restrict__ frow = (const ulonglong2*)feat;  // 32 per row

    int  seg = __ldg(mem + astart);
    bool began_inside = (astart == 0) || (__ldg(mem + astart - 1) != seg);

    unsigned long long s01 = 0, s23 = 0;   // packed f32x2 sums
    float4 m = make_float4(-CUDART_INF_F, -CUDART_INF_F, -CUDART_INF_F, -CUDART_INF_F);
    int cnt = 0;

    auto flush = [&](int sg, bool full) {
        float2 a = unpack2(s01), b = unpack2(s23);
        float* om = out + (size_t)sg * 256 + lane * 4;   // mean slot
        float* ox = om + 128;                            // max slot
        if (full) {
            float r = 1.0f / (float)cnt;
            *(float4*)om = make_float4(a.x * r, a.y * r, b.x * r, b.y * r);
            *(float4*)ox = m;
        } else {
            atomicAdd(om + 0, a.x); atomicAdd(om + 1, a.y);
            atomicAdd(om + 2, b.x); atomicAdd(om + 3, b.y);
            atomic_max_float(ox + 0, m.x); atomic_max_float(ox + 1, m.y);
            atomic_max_float(ox + 2, m.z); atomic_max_float(ox + 3, m.w);
            if (lane == 0) {
                atomicAdd(&g_counts[sg], (float)cnt);
                g_flag[sg] = 1;
            }
        }
    };
    auto reset = [&]() {
        s01 = 0; s23 = 0;
        m = make_float4(-CUDART_INF_F, -CUDART_INF_F, -CUDART_INF_F, -CUDART_INF_F);
        cnt = 0;
    };
    auto accum = [&](ulonglong2 v) {
        f32x2_add(s01, v.x);
        f32x2_add(s23, v.y);
        float2 a = unpack2(v.x), b = unpack2(v.y);
        m.x = fmaxf(m.x, a.x); m.y = fmaxf(m.y, a.y);
        m.z = fmaxf(m.z, b.x); m.w = fmaxf(m.w, b.y);
    };

    long long a = astart;
    for (; a + 8 <= aend; a += 8) {
        int4 mb0 = *(const int4*)(mem + a);
        int4 mb1 = *(const int4*)(mem + a + 4);
        ulonglong2 vv[8];
#pragma unroll
        for (int u = 0; u < 8; ++u)
            vv[u] = __ldg(&frow[(a + u) * 32 + lane]);

        if (mb0.x == mb1.w) {
            // whole batch is one segment (membership sorted)
            if (mb0.x != seg) {
                flush(seg, began_inside);
                began_inside = true;
                seg = mb0.x;
                reset();
            }
#pragma unroll
            for (int u = 0; u < 8; ++u) accum(vv[u]);
            cnt += 8;
        } else {
            int mbs[8] = {mb0.x, mb0.y, mb0.z, mb0.w, mb1.x, mb1.y, mb1.z, mb1.w};
#pragma unroll
            for (int u = 0; u < 8; ++u) {
                if (mbs[u] != seg) {
                    flush(seg, began_inside);
                    began_inside = true;
                    seg = mbs[u];
                    reset();
                }
                accum(vv[u]);
                ++cnt;
            }
        }
    }
    // Scalar tail (last warp only, when n not divisible by 8)
    for (; a < aend; ++a) {
        int mb = __ldg(mem + a);
        ulonglong2 v = __ldg(&frow[a * 32 + lane]);
        if (mb != seg) {
            flush(seg, began_inside);
            began_inside = true;
            seg = mb;
            reset();
        }
        accum(v);
        ++cnt;
    }

    bool ended_inside = (aend == n_atoms) || (__ldg(mem + aend) != seg);
    flush(seg, began_inside && ended_inside);
}

// ---------------------------------------------------------------------------
// Finalize: divide mean by count for boundary-flagged segments only.
// ---------------------------------------------------------------------------
__global__ void gg_fin(float4* __restrict__ out4, int batch) {
    int i = blockIdx.x * blockDim.x + threadIdx.x;
    int total = batch * 32;
    if (i >= total) return;
    int sg = i >> 5;
    if (!g_flag[sg]) return;
    int f = i & 31;
    float r = 1.0f / g_counts[sg];
    float4 v = out4[(size_t)sg * 64 + f];
    v.x *= r; v.y *= r; v.z *= r; v.w *= r;
    out4[(size_t)sg * 64 + f] = v;
}

// ---------------------------------------------------------------------------
extern "C" void kernel_launch(void* const* d_in, const int* in_sizes, int n_in,
                              void* d_out, int out_size) {
    const float* feat = (const float*)d_in[0];
    const int*   mem  = (const int*)d_in[1];
    float*       out  = (float*)d_out;

    int n_atoms = in_sizes[1];          // membership element count
    int batch   = out_size / 256;       // output rows ([batch, 2*128])

    // Exactly-balanced single wave: SM_count * BLOCKS_PER_SM blocks, 8 warps each.
    int sm_count = 152;
    cudaDeviceGetAttribute(&sm_count, cudaDevAttrMultiProcessorCount, 0);
    int nblocks = sm_count * BLOCKS_PER_SM;
    long long nwarps = (long long)nblocks * (THREADS_MAIN / 32);
    long long chunk_ll = (n_atoms + nwarps - 1) / nwarps;
    int chunk = (int)((chunk_ll + 7) / 8) * 8;   // multiple of 8 (int4 alignment)

    int init_total = batch * 32;
    gg_init<<<(init_total + 255) / 256, 256>>>((float4*)out, batch);

    gg_main<<<nblocks, THREADS_MAIN>>>(feat, mem, out, n_atoms, chunk);

    int fin_total = batch * 32;
    gg_fin<<<(fin_total + 255) / 256, 256>>>((float4*)out, batch);
}

// round 6
// speedup vs baseline: 1.1997x; 1.0285x over previous
#include <cuda_runtime.h>
#include <math_constants.h>

#define THREADS_MAIN 256    // 8 warps per block
#define BLOCKS_PER_SM 2
#define MAXW 4096           // max warps supported (grid capped accordingly)

// Per-warp boundary partial records (rewritten fully each launch).
__device__ float4 g_sH[MAXW][32];   // head partial sums
__device__ float4 g_mH[MAXW][32];   // head partial maxs
__device__ int    g_cH[MAXW];       // head partial count
__device__ int    g_segH[MAXW];     // head segment id (-1 = none)
__device__ int    g_ptH[MAXW];      // head is pass-through (whole chunk, open both ends)
__device__ float4 g_sT[MAXW][32];   // tail partial sums (owner records)
__device__ float4 g_mT[MAXW][32];
__device__ int    g_cT[MAXW];
__device__ int    g_segT[MAXW];     // tail segment id (-1 = none/owner elsewhere)

__device__ __forceinline__ void f32x2_add(unsigned long long& acc, unsigned long long v) {
    asm("add.rn.f32x2 %0, %0, %1;" : "+l"(acc) : "l"(v));
}
__device__ __forceinline__ float2 unpack2(unsigned long long v) {
    float a, b;
    asm("mov.b64 {%0,%1}, %2;" : "=f"(a), "=f"(b) : "l"(v));
    return make_float2(a, b);
}

// ---------------------------------------------------------------------------
// Main: warp-per-chunk segmented scan. Lane l owns features [4l,4l+4).
// Interior segments -> direct full store (mean divided in place).
// Head/tail boundary segments -> partial records in scratch; no atomics,
// no output pre-initialization needed.
// ---------------------------------------------------------------------------
__global__ void gg_main(const float* __restrict__ feat,
                        const int*   __restrict__ mem,
                        float*       __restrict__ out,
                        int n_atoms, int chunk) {
    const int lane = threadIdx.x & 31;
    const int wg   = (blockIdx.x * blockDim.x + threadIdx.x) >> 5;
    long long astart = (long long)wg * chunk;
    if (astart >= n_atoms) {
        if (lane == 0) { g_segH[wg] = -1; g_segT[wg] = -1; }
        return;
    }
    long long aend = astart + chunk;
    if (aend > n_atoms) aend = n_atoms;

    const ulonglong2* __restrict__ frow = (const ulonglong2*)feat;  // 32 per row

    int  seg = __ldg(mem + astart);
    bool began_inside = (astart == 0) || (__ldg(mem + astart - 1) != seg);
    bool wrote_head = false;

    unsigned long long s01 = 0, s23 = 0;   // packed f32x2 sums
    float4 m = make_float4(-CUDART_INF_F, -CUDART_INF_F, -CUDART_INF_F, -CUDART_INF_F);
    int cnt = 0;

    auto store_full = [&](int sg) {
        float2 a = unpack2(s01), b = unpack2(s23);
        float r = 1.0f / (float)cnt;
        float* om = out + (size_t)sg * 256 + lane * 4;
        *(float4*)om         = make_float4(a.x * r, a.y * r, b.x * r, b.y * r);
        *(float4*)(om + 128) = m;
    };
    auto store_head = [&](int sg, int pt) {
        float2 a = unpack2(s01), b = unpack2(s23);
        g_sH[wg][lane] = make_float4(a.x, a.y, b.x, b.y);
        g_mH[wg][lane] = m;
        if (lane == 0) { g_cH[wg] = cnt; g_segH[wg] = sg; g_ptH[wg] = pt; }
        wrote_head = true;
    };
    auto store_tail = [&](int sg) {
        float2 a = unpack2(s01), b = unpack2(s23);
        g_sT[wg][lane] = make_float4(a.x, a.y, b.x, b.y);
        g_mT[wg][lane] = m;
        if (lane == 0) { g_cT[wg] = cnt; g_segT[wg] = sg; }
    };
    auto flush_mid = [&](int sg) {     // segment ended inside the chunk
        if (began_inside) store_full(sg);
        else              store_head(sg, 0);
        began_inside = true;
    };
    auto reset = [&]() {
        s01 = 0; s23 = 0;
        m = make_float4(-CUDART_INF_F, -CUDART_INF_F, -CUDART_INF_F, -CUDART_INF_F);
        cnt = 0;
    };
    auto accum = [&](ulonglong2 v) {
        f32x2_add(s01, v.x);
        f32x2_add(s23, v.y);
        float2 a = unpack2(v.x), b = unpack2(v.y);
        m.x = fmaxf(m.x, a.x); m.y = fmaxf(m.y, a.y);
        m.z = fmaxf(m.z, b.x); m.w = fmaxf(m.w, b.y);
    };

    long long a = astart;
    for (; a + 8 <= aend; a += 8) {
        int4 mb0 = *(const int4*)(mem + a);
        int4 mb1 = *(const int4*)(mem + a + 4);
        ulonglong2 vv[8];
#pragma unroll
        for (int u = 0; u < 8; ++u)
            vv[u] = __ldg(&frow[(a + u) * 32 + lane]);

        if (mb0.x == mb1.w) {
            // whole 8-batch is one segment (membership sorted)
            if (mb0.x != seg) { flush_mid(seg); seg = mb0.x; reset(); }
#pragma unroll
            for (int u = 0; u < 8; ++u) accum(vv[u]);
            cnt += 8;
        } else {
            int mbs[8] = {mb0.x, mb0.y, mb0.z, mb0.w, mb1.x, mb1.y, mb1.z, mb1.w};
#pragma unroll
            for (int u = 0; u < 8; ++u) {
                if (mbs[u] != seg) { flush_mid(seg); seg = mbs[u]; reset(); }
                accum(vv[u]);
                ++cnt;
            }
        }
    }
    for (; a < aend; ++a) {     // scalar tail (last active warp only)
        int mb = __ldg(mem + a);
        ulonglong2 v = __ldg(&frow[a * 32 + lane]);
        if (mb != seg) { flush_mid(seg); seg = mb; reset(); }
        accum(v);
        ++cnt;
    }

    bool ended_inside = (aend == n_atoms) || (__ldg(mem + aend) != seg);
    if (ended_inside) {
        if (began_inside) store_full(seg);
        else              store_head(seg, 0);
        if (lane == 0) g_segT[wg] = -1;                  // no tail record
    } else {
        if (began_inside) store_tail(seg);               // this warp owns it
        else { store_head(seg, 1);                       // pass-through chunk
               if (lane == 0) g_segT[wg] = -1; }
    }
    if (!wrote_head && (began_inside || ended_inside)) {
        // ensure head record invalid when none was written
        if (lane == 0 && g_segT[wg] != -12345) { /* no-op to keep structure */ }
    }
    if (!wrote_head) { if (lane == 0) g_segH[wg] = (wrote_head ? g_segH[wg] : -1); }
    // NOTE: head validity — if a head record was written above, g_segH holds it;
    // otherwise mark invalid:
    if (lane == 0 && !wrote_head) g_segH[wg] = -1;
}

// ---------------------------------------------------------------------------
// Combine: one warp per owner record. Merge tail[w] with head[w+1...] chain,
// then write the straddling segment's output row (exactly once).
// ---------------------------------------------------------------------------
__global__ void gg_combine(float* __restrict__ out, int nwarps) {
    int t = blockIdx.x * blockDim.x + threadIdx.x;
    int w = t >> 5, lane = t & 31;
    if (w >= nwarps) return;
    int seg = g_segT[w];
    if (seg < 0) return;

    float4 s = g_sT[w][lane];
    float4 m = g_mT[w][lane];
    int  cnt = g_cT[w];

    for (int j = w + 1; j < nwarps; ++j) {
        if (g_segH[j] != seg) break;
        float4 hs = g_sH[j][lane], hm = g_mH[j][lane];
        s.x += hs.x; s.y += hs.y; s.z += hs.z; s.w += hs.w;
        m.x = fmaxf(m.x, hm.x); m.y = fmaxf(m.y, hm.y);
        m.z = fmaxf(m.z, hm.z); m.w = fmaxf(m.w, hm.w);
        cnt += g_cH[j];
        if (!g_ptH[j]) break;   // segment ended inside warp j
    }

    float r = 1.0f / (float)cnt;
    float* om = out + (size_t)seg * 256 + lane * 4;
    *(float4*)om         = make_float4(s.x * r, s.y * r, s.z * r, s.w * r);
    *(float4*)(om + 128) = m;
}

// ---------------------------------------------------------------------------
extern "C" void kernel_launch(void* const* d_in, const int* in_sizes, int n_in,
                              void* d_out, int out_size) {
    const float* feat = (const float*)d_in[0];
    const int*   mem  = (const int*)d_in[1];
    float*       out  = (float*)d_out;

    int n_atoms = in_sizes[1];          // membership element count

    // Exactly-balanced single wave: SM_count * BLOCKS_PER_SM blocks, 8 warps each.
    int sm_count = 152;
    cudaDeviceGetAttribute(&sm_count, cudaDevAttrMultiProcessorCount, 0);
    int nblocks = sm_count * BLOCKS_PER_SM;
    int max_blocks = MAXW / (THREADS_MAIN / 32);
    if (nblocks > max_blocks) nblocks = max_blocks;
    int nwarps = nblocks * (THREADS_MAIN / 32);
    long long chunk_ll = ((long long)n_atoms + nwarps - 1) / nwarps;
    int chunk = (int)((chunk_ll + 7) / 8) * 8;   // multiple of 8 (int4 alignment)

    gg_main<<<nblocks, THREADS_MAIN>>>(feat, mem, out, n_atoms, chunk);

    int comb_threads = nwarps * 32;
    gg_combine<<<(comb_threads + 255) / 256, 256>>>(out, nwarps);
}

// round 7
// speedup vs baseline: 1.2047x; 1.0042x over previous
#include <cuda_runtime.h>
#include <math_constants.h>

#define THREADS_MAIN 256    // 8 warps per block
#define BLOCKS_PER_SM 2
#define MAXW 4096           // max warps supported (grid capped accordingly)

// Per-warp boundary partial records (fully rewritten every launch).
__device__ float4 g_sH[MAXW][32];   // head partial sums
__device__ float4 g_mH[MAXW][32];   // head partial maxs
__device__ int    g_cH[MAXW];       // head partial count
__device__ int    g_segH[MAXW];     // head segment id (-1 = none)
__device__ int    g_ptH[MAXW];      // head is pass-through (open both ends)
__device__ float4 g_sT[MAXW][32];   // tail partial sums (owner records)
__device__ float4 g_mT[MAXW][32];
__device__ int    g_cT[MAXW];
__device__ int    g_segT[MAXW];     // tail segment id (-1 = none)

__device__ __forceinline__ void f32x2_add(unsigned long long& acc, unsigned long long v) {
    asm("add.rn.f32x2 %0, %0, %1;" : "+l"(acc) : "l"(v));
}
__device__ __forceinline__ float2 unpack2(unsigned long long v) {
    float a, b;
    asm("mov.b64 {%0,%1}, %2;" : "=f"(a), "=f"(b) : "l"(v));
    return make_float2(a, b);
}

// ---------------------------------------------------------------------------
// Main: warp-per-chunk segmented scan. Lane l owns features [4l,4l+4).
// Interior segments -> direct full store (mean divided in place).
// Head partial is buffered in REGISTERS and published, with the tail record,
// only at kernel end -> records are L2-hot when gg_combine reads them.
// ---------------------------------------------------------------------------
__global__ void __launch_bounds__(THREADS_MAIN)
gg_main(const float* __restrict__ feat,
        const int*   __restrict__ mem,
        float*       __restrict__ out,
        int n_atoms, int chunk) {
    const int lane = threadIdx.x & 31;
    const int wg   = (blockIdx.x * blockDim.x + threadIdx.x) >> 5;
    long long astart = (long long)wg * chunk;
    if (astart >= n_atoms) {
        if (lane == 0) { g_segH[wg] = -1; g_segT[wg] = -1; }
        return;
    }
    long long aend = astart + chunk;
    if (aend > n_atoms) aend = n_atoms;

    const ulonglong2* __restrict__ frow = (const ulonglong2*)feat;  // 32 per row

    int  seg = __ldg(mem + astart);
    bool began_inside = (astart == 0) || (__ldg(mem + astart - 1) != seg);

    unsigned long long s01 = 0, s23 = 0;   // packed f32x2 sums
    float4 m = make_float4(-CUDART_INF_F, -CUDART_INF_F, -CUDART_INF_F, -CUDART_INF_F);
    int cnt = 0;

    // Head partial buffered in registers until the end.
    int    hseg = -1, hpt = 0, hcnt = 0;
    float4 hsum = make_float4(0.f, 0.f, 0.f, 0.f);
    float4 hmax = hsum;

    auto store_full = [&](int sg) {
        float2 a = unpack2(s01), b = unpack2(s23);
        float r = 1.0f / (float)cnt;
        float* om = out + (size_t)sg * 256 + lane * 4;
        *(float4*)om         = make_float4(a.x * r, a.y * r, b.x * r, b.y * r);
        *(float4*)(om + 128) = m;
    };
    auto buffer_head = [&](int sg, int pt) {
        float2 a = unpack2(s01), b = unpack2(s23);
        hsum = make_float4(a.x, a.y, b.x, b.y);
        hmax = m; hcnt = cnt; hseg = sg; hpt = pt;
    };
    auto flush_mid = [&](int sg) {       // segment ended inside the chunk
        if (began_inside) store_full(sg);
        else              buffer_head(sg, 0);
        began_inside = true;
    };
    auto reset = [&]() {
        s01 = 0; s23 = 0;
        m = make_float4(-CUDART_INF_F, -CUDART_INF_F, -CUDART_INF_F, -CUDART_INF_F);
        cnt = 0;
    };
    auto accum = [&](ulonglong2 v) {
        f32x2_add(s01, v.x);
        f32x2_add(s23, v.y);
        float2 a = unpack2(v.x), b = unpack2(v.y);
        m.x = fmaxf(m.x, a.x); m.y = fmaxf(m.y, a.y);
        m.z = fmaxf(m.z, b.x); m.w = fmaxf(m.w, b.y);
    };

    long long a = astart;
    for (; a + 8 <= aend; a += 8) {
        int4 mb0 = *(const int4*)(mem + a);
        int4 mb1 = *(const int4*)(mem + a + 4);
        ulonglong2 vv[8];
#pragma unroll
        for (int u = 0; u < 8; ++u)
            vv[u] = __ldg(&frow[(a + u) * 32 + lane]);

        if (mb0.x == mb1.w) {
            // whole 8-batch is one segment (membership sorted)
            if (mb0.x != seg) { flush_mid(seg); seg = mb0.x; reset(); }
#pragma unroll
            for (int u = 0; u < 8; ++u) accum(vv[u]);
            cnt += 8;
        } else {
            int mbs[8] = {mb0.x, mb0.y, mb0.z, mb0.w, mb1.x, mb1.y, mb1.z, mb1.w};
#pragma unroll
            for (int u = 0; u < 8; ++u) {
                if (mbs[u] != seg) { flush_mid(seg); seg = mbs[u]; reset(); }
                accum(vv[u]);
                ++cnt;
            }
        }
    }
    for (; a < aend; ++a) {     // scalar tail (last active warp only)
        int mb = __ldg(mem + a);
        ulonglong2 v = __ldg(&frow[a * 32 + lane]);
        if (mb != seg) { flush_mid(seg); seg = mb; reset(); }
        accum(v);
        ++cnt;
    }

    bool ended_inside = (aend == n_atoms) || (__ldg(mem + aend) != seg);
    int tseg = -1;
    if (ended_inside) {
        if (began_inside) store_full(seg);
        else              buffer_head(seg, 0);
    } else {
        if (began_inside) tseg = seg;            // tail owner: current regs
        else              buffer_head(seg, 1);   // pass-through chunk
    }

    // ---- publish all boundary records now (L2-hot for gg_combine) ----
    if (tseg >= 0) {
        float2 a2 = unpack2(s01), b2 = unpack2(s23);
        g_sT[wg][lane] = make_float4(a2.x, a2.y, b2.x, b2.y);
        g_mT[wg][lane] = m;
        if (lane == 0) g_cT[wg] = cnt;
    }
    if (hseg >= 0) {
        g_sH[wg][lane] = hsum;
        g_mH[wg][lane] = hmax;
        if (lane == 0) { g_cH[wg] = hcnt; g_ptH[wg] = hpt; }
    }
    if (lane == 0) { g_segT[wg] = tseg; g_segH[wg] = hseg; }
}

// ---------------------------------------------------------------------------
// Combine: one warp per owner record. Merge tail[w] with head[w+1...] chain,
// then write the straddling segment's output row (exactly once).
// ---------------------------------------------------------------------------
__global__ void gg_combine(float* __restrict__ out, int nwarps) {
    int t = blockIdx.x * blockDim.x + threadIdx.x;
    int w = t >> 5, lane = t & 31;
    if (w >= nwarps) return;
    int seg = g_segT[w];
    if (seg < 0) return;

    float4 s = g_sT[w][lane];
    float4 m = g_mT[w][lane];
    int  cnt = g_cT[w];

    for (int j = w + 1; j < nwarps; ++j) {
        if (g_segH[j] != seg) break;
        float4 hs = g_sH[j][lane], hm = g_mH[j][lane];
        s.x += hs.x; s.y += hs.y; s.z += hs.z; s.w += hs.w;
        m.x = fmaxf(m.x, hm.x); m.y = fmaxf(m.y, hm.y);
        m.z = fmaxf(m.z, hm.z); m.w = fmaxf(m.w, hm.w);
        cnt += g_cH[j];
        if (!g_ptH[j]) break;   // segment ended inside warp j
    }

    float r = 1.0f / (float)cnt;
    float* om = out + (size_t)seg * 256 + lane * 4;
    *(float4*)om         = make_float4(s.x * r, s.y * r, s.z * r, s.w * r);
    *(float4*)(om + 128) = m;
}

// ---------------------------------------------------------------------------
extern "C" void kernel_launch(void* const* d_in, const int* in_sizes, int n_in,
                              void* d_out, int out_size) {
    const float* feat = (const float*)d_in[0];
    const int*   mem  = (const int*)d_in[1];
    float*       out  = (float*)d_out;

    int n_atoms = in_sizes[1];          // membership element count

    // Exactly-balanced single wave: SM_count * BLOCKS_PER_SM blocks, 8 warps each.
    int sm_count = 152;
    cudaDeviceGetAttribute(&sm_count, cudaDevAttrMultiProcessorCount, 0);
    int nblocks = sm_count * BLOCKS_PER_SM;
    int max_blocks = MAXW / (THREADS_MAIN / 32);
    if (nblocks > max_blocks) nblocks = max_blocks;
    int nwarps = nblocks * (THREADS_MAIN / 32);
    long long chunk_ll = ((long long)n_atoms + nwarps - 1) / nwarps;
    int chunk = (int)((chunk_ll + 7) / 8) * 8;   // multiple of 8 (int4 alignment)

    gg_main<<<nblocks, THREADS_MAIN>>>(feat, mem, out, n_atoms, chunk);

    int comb_threads = nwarps * 32;
    gg_combine<<<(comb_threads + 255) / 256, 256>>>(out, nwarps);
}